// round 15
// baseline (speedup 1.0000x reference)
#include <cuda_runtime.h>
#include <cuda_fp16.h>
#include <cstdint>

#define EMBED 256
#define HEADS 8
#define HD    32
#define NTOK  2304
#define BATCH 4
#define HH    48
#define WW    48
#define KSCALE 0.17677669529663687f  /* 32^-0.5 */
#define LOG2E  1.4426950408889634f

// Tensor GEMM tiling
#define GBM 128
#define GBN 64
#define GBK 32
#define ASTR 36
#define WTSTR 36
#define GEMM_SMEM ((2 * GBM * ASTR + 2 * GBN * WTSTR) * 4)

// Attention tiling
#define TQ 128
#define TK 64
#define KVH 20            // K/V fp16 tile row stride in u32
#define MSTR 72           // mask smem row stride in u32 (64 + 8: LDS.64 conflict-free)
#define NKT (NTOK / TK)
#define H2_ONES 0x3C003C00u

// attn smem partition (u32 words)
#define KOFF 0
#define VOFF (3 * TK * KVH)                    // 3840
#define MOFF (VOFF + 3 * TK * KVH)             // 7680
#define ATTN_WORDS (MOFF + 2 * TQ * MSTR)      // 26112
#define ATTN_SMEM (ATTN_WORDS * 4)             // 104448 B

// round_all partition
#define NXB 2304
#define NWB 1024

// Scratch buffers (allocation-free rule: __device__ globals)
__device__ float  g_xt[BATCH * NTOK * EMBED];
__device__ float  g_wt[4 * EMBED * EMBED];     // tf32-rounded, TRANSPOSED [n][k]
__device__ __half g_qh[BATCH * NTOK * EMBED];  // fp16 rope(q)*log2e
__device__ __half g_kh[BATCH * NTOK * EMBED];  // fp16 rope(k)*KSCALE
__device__ float  g_v[BATCH * NTOK * EMBED];   // exact v (for lepe)
__device__ __half g_vh[BATCH * NTOK * EMBED];  // fp16 v (for attn PV)
__device__ float  g_lepe[BATCH * NTOK * EMBED];
__device__ float  g_ao[BATCH * NTOK * EMBED];

// ---------------------------------------------------------------------------
// Helpers
// ---------------------------------------------------------------------------
__device__ __forceinline__ uint32_t f2tf32(float x) {
    uint32_t r;
    asm("cvt.rna.tf32.f32 %0, %1;" : "=r"(r) : "f"(x));
    return r;
}

__device__ __forceinline__ uint32_t pack_h2(float lo, float hi) {
    uint32_t r;
    asm("cvt.rn.f16x2.f32 %0, %1, %2;" : "=r"(r) : "f"(hi), "f"(lo));
    return r;
}

__device__ __forceinline__ uint32_t ex2_h2(uint32_t h2) {
    uint32_t r;
    asm("ex2.approx.f16x2 %0, %1;" : "=r"(r) : "r"(h2));
    return r;
}

__device__ __forceinline__ void mma_tf32(
    float& c0, float& c1, float& c2, float& c3,
    uint32_t a0, uint32_t a1, uint32_t a2, uint32_t a3,
    uint32_t b0, uint32_t b1)
{
    asm("mma.sync.aligned.m16n8k8.row.col.f32.tf32.tf32.f32 "
        "{%0,%1,%2,%3}, {%4,%5,%6,%7}, {%8,%9}, {%0,%1,%2,%3};"
        : "+f"(c0), "+f"(c1), "+f"(c2), "+f"(c3)
        : "r"(a0), "r"(a1), "r"(a2), "r"(a3), "r"(b0), "r"(b1));
}

__device__ __forceinline__ void mma_f16(
    float& c0, float& c1, float& c2, float& c3,
    uint32_t a0, uint32_t a1, uint32_t a2, uint32_t a3,
    uint32_t b0, uint32_t b1)
{
    asm("mma.sync.aligned.m16n8k16.row.col.f32.f16.f16.f32 "
        "{%0,%1,%2,%3}, {%4,%5,%6,%7}, {%8,%9}, {%0,%1,%2,%3};"
        : "+f"(c0), "+f"(c1), "+f"(c2), "+f"(c3)
        : "r"(a0), "r"(a1), "r"(a2), "r"(a3), "r"(b0), "r"(b1));
}

__device__ __forceinline__ void cp16(uint32_t s_addr, const void* g_ptr) {
    asm volatile("cp.async.ca.shared.global [%0], [%1], 16;"
                 :: "r"(s_addr), "l"(g_ptr));
}

__device__ __forceinline__ void ldsm4(
    uint32_t& r0, uint32_t& r1, uint32_t& r2, uint32_t& r3, uint32_t addr)
{
    asm volatile("ldmatrix.sync.aligned.m8n8.x4.shared.b16 {%0,%1,%2,%3}, [%4];"
        : "=r"(r0), "=r"(r1), "=r"(r2), "=r"(r3) : "r"(addr));
}

__device__ __forceinline__ void ldsm4t(
    uint32_t& r0, uint32_t& r1, uint32_t& r2, uint32_t& r3, uint32_t addr)
{
    asm volatile("ldmatrix.sync.aligned.m8n8.x4.trans.shared.b16 {%0,%1,%2,%3}, [%4];"
        : "=r"(r0), "=r"(r1), "=r"(r2), "=r"(r3) : "r"(addr));
}

// ---------------------------------------------------------------------------
// round_all: tf32-round x + tf32-round AND TRANSPOSE weights.
// ---------------------------------------------------------------------------
__global__ void __launch_bounds__(256)
round_all(const float* __restrict__ x,
          const float* __restrict__ wq, const float* __restrict__ wk,
          const float* __restrict__ wv, const float* __restrict__ wo)
{
    const int bid = blockIdx.x;
    if (bid < NXB) {
        const int i = bid * 256 + threadIdx.x;
        float4 v = ((const float4*)x)[i];
        float4 o;
        o.x = __uint_as_float(f2tf32(v.x));
        o.y = __uint_as_float(f2tf32(v.y));
        o.z = __uint_as_float(f2tf32(v.z));
        o.w = __uint_as_float(f2tf32(v.w));
        ((float4*)g_xt)[i] = o;
    } else {
        const int idx = (bid - NXB) * 256 + threadIdx.x;
        const int mat = idx >> 16;
        const int rem = idx & 65535;
        const int n   = rem >> 8;
        const int k   = rem & 255;
        const float* src = (mat == 0) ? wq : (mat == 1) ? wk
                         : (mat == 2) ? wv : wo;
        g_wt[(size_t)mat * 65536 + n * 256 + k] =
            __uint_as_float(f2tf32(src[k * 256 + n]));
    }
}

// ---------------------------------------------------------------------------
// TF32 tensor GEMM (unchanged, passing).
// ---------------------------------------------------------------------------
__device__ __forceinline__ void gemm_t_body(
    const float* __restrict__ A, const float* __restrict__ WT,
    const float* __restrict__ bias, float* __restrict__ C,
    int m0, int n0, int mode,
    const float* __restrict__ sin_t, const float* __restrict__ cos_t,
    __half* __restrict__ Ch)
{
    extern __shared__ __align__(16) uint32_t dynsmem[];
    uint32_t* a_s = dynsmem;
    uint32_t* w_s = dynsmem + 2 * GBM * ASTR;

    const int tid  = threadIdx.x;
    const int warp = tid >> 5;
    const int lane = tid & 31;
    const int g    = lane >> 2;
    const int t4   = lane & 3;
    const int li   = lane & 7;
    const int sub  = lane >> 3;
    const int wrow = warp * 16;

    const uint32_t a_smem0 = (uint32_t)__cvta_generic_to_shared(a_s);
    const uint32_t w_smem0 = (uint32_t)__cvta_generic_to_shared(w_s);
    const uint32_t a_lane = a_smem0 +
        (((wrow + li + (sub & 1) * 8) * ASTR + (sub >> 1) * 4) << 2);
    const uint32_t w_lane = w_smem0 + ((li * WTSTR + sub * 4) << 2);
    const uint32_t ABUF = GBM * ASTR * 4;
    const uint32_t WBUF = GBN * WTSTR * 4;

    float acc[8][4] = {};

    #define GEMM_ISSUE(kt, buf)                                               \
    {                                                                         \
        _Pragma("unroll")                                                     \
        for (int j = 0; j < 4; j++) {                                         \
            const int idx = j * 256 + tid;                                    \
            const int r = idx >> 3, c4 = (idx & 7) << 2;                      \
            cp16(a_smem0 + (buf) * ABUF + ((r * ASTR + c4) << 2),             \
                 &A[(size_t)(m0 + r) * EMBED + (kt) * GBK + c4]);             \
        }                                                                     \
        _Pragma("unroll")                                                     \
        for (int j = 0; j < 2; j++) {                                         \
            const int idx = j * 256 + tid;                                    \
            const int r = idx >> 3, c4 = (idx & 7) << 2;                      \
            cp16(w_smem0 + (buf) * WBUF + ((r * WTSTR + c4) << 2),            \
                 &WT[(size_t)(n0 + r) * EMBED + (kt) * GBK + c4]);            \
        }                                                                     \
        asm volatile("cp.async.commit_group;");                               \
    }

    GEMM_ISSUE(0, 0)

    #pragma unroll 1
    for (int kt = 0; kt < EMBED / GBK; kt++) {
        const int cur = kt & 1;
        asm volatile("cp.async.wait_group 0;");
        __syncthreads();
        if (kt + 1 < EMBED / GBK) GEMM_ISSUE(kt + 1, cur ^ 1)

        const uint32_t ap = a_lane + cur * ABUF;
        const uint32_t wp = w_lane + cur * WBUF;
        #pragma unroll
        for (int kcp = 0; kcp < 2; kcp++) {
            uint32_t aA[4], aB[4];
            ldsm4(aA[0], aA[1], aA[2], aA[3], ap + kcp * 64);
            ldsm4(aB[0], aB[1], aB[2], aB[3], ap + kcp * 64 + 32);
            #pragma unroll
            for (int n = 0; n < 8; n++) {
                uint32_t b[4];
                ldsm4(b[0], b[1], b[2], b[3],
                      wp + n * (8 * WTSTR * 4) + kcp * 64);
                mma_tf32(acc[n][0], acc[n][1], acc[n][2], acc[n][3],
                         aA[0], aA[1], aA[2], aA[3], b[0], b[1]);
                mma_tf32(acc[n][0], acc[n][1], acc[n][2], acc[n][3],
                         aB[0], aB[1], aB[2], aB[3], b[2], b[3]);
            }
        }
    }
    #undef GEMM_ISSUE

    const int row0 = m0 + wrow + g;
    const int row1 = row0 + 8;
    const int pos0 = row0 % NTOK;
    const int pos1 = row1 % NTOK;

    #pragma unroll
    for (int n = 0; n < 8; n++) {
        const int col = n0 + n * 8 + 2 * t4;
        const float b0 = bias[col], b1 = bias[col + 1];
        float e0 = acc[n][0] + b0, o0 = acc[n][1] + b1;
        float e1 = acc[n][2] + b0, o1 = acc[n][3] + b1;

        if (mode == 1 || mode == 2) {
            const int dd = col & (HD - 1);
            float2 cs0 = *(const float2*)&cos_t[pos0 * HD + dd];
            float2 sn0 = *(const float2*)&sin_t[pos0 * HD + dd];
            float2 cs1 = *(const float2*)&cos_t[pos1 * HD + dd];
            float2 sn1 = *(const float2*)&sin_t[pos1 * HD + dd];
            const float sc = (mode == 1) ? LOG2E : KSCALE;
            float r0e = (e0 * cs0.x - o0 * sn0.x) * sc;
            float r0o = (o0 * cs0.y + e0 * sn0.y) * sc;
            float r1e = (e1 * cs1.x - o1 * sn1.x) * sc;
            float r1o = (o1 * cs1.y + e1 * sn1.y) * sc;
            *(uint32_t*)&Ch[(size_t)row0 * EMBED + col] = pack_h2(r0e, r0o);
            *(uint32_t*)&Ch[(size_t)row1 * EMBED + col] = pack_h2(r1e, r1o);
        } else {
            *(float2*)&C[(size_t)row0 * EMBED + col] = make_float2(e0, o0);
            *(float2*)&C[(size_t)row1 * EMBED + col] = make_float2(e1, o1);
            if (mode == 3) {
                *(uint32_t*)&Ch[(size_t)row0 * EMBED + col] = pack_h2(e0, o0);
                *(uint32_t*)&Ch[(size_t)row1 * EMBED + col] = pack_h2(e1, o1);
            }
        }
    }
}

__global__ void __launch_bounds__(256, 2)
qkv_gemm_t(const float* __restrict__ bq, const float* __restrict__ bk,
           const float* __restrict__ bv,
           const float* __restrict__ sin_t, const float* __restrict__ cos_t)
{
    const int m0  = blockIdx.y * GBM;
    const int nb  = blockIdx.x;
    const int mat = nb >> 2;
    const int n0  = (nb & 3) * GBN;

    if (mat == 0)
        gemm_t_body(g_xt, g_wt, bq, nullptr, m0, n0, 1, sin_t, cos_t, g_qh);
    else if (mat == 1)
        gemm_t_body(g_xt, g_wt + (size_t)EMBED * EMBED, bk, nullptr,
                    m0, n0, 2, sin_t, cos_t, g_kh);
    else
        gemm_t_body(g_xt, g_wt + (size_t)2 * EMBED * EMBED, bv, g_v,
                    m0, n0, 3, nullptr, nullptr, g_vh);
}

__global__ void __launch_bounds__(256, 2)
out_gemm_t(const float* __restrict__ bout, float* __restrict__ out)
{
    gemm_t_body(g_ao, g_wt + (size_t)3 * EMBED * EMBED, bout, out,
                blockIdx.y * GBM, blockIdx.x * GBN, 0,
                nullptr, nullptr, nullptr);
}

// ---------------------------------------------------------------------------
// LePE: 5x5 depthwise conv, register sliding window.
// ---------------------------------------------------------------------------
__global__ void __launch_bounds__(256)
lepe_kernel(const float* __restrict__ w, const float* __restrict__ bias)
{
    const int c  = threadIdx.x;
    const int y  = blockIdx.x;
    const int b  = blockIdx.y;
    const int x0 = blockIdx.z * 6;

    float wr[25];
    #pragma unroll
    for (int t = 0; t < 25; t++) wr[t] = w[t * EMBED + c];
    const float bv = bias[c];

    const float* vb = g_v + (size_t)b * NTOK * EMBED;
    float* ob = g_lepe + (size_t)(b * NTOK + y * WW) * EMBED;

    float win[5][5];
    #pragma unroll
    for (int j = 0; j < 4; j++) {
        const int xx = x0 - 2 + j;
        #pragma unroll
        for (int dy = 0; dy < 5; dy++) {
            const int yy = y + dy - 2;
            win[dy][j] = (xx >= 0 && xx < WW && yy >= 0 && yy < HH)
                       ? vb[(size_t)(yy * WW + xx) * EMBED + c] : 0.f;
        }
    }

    #pragma unroll
    for (int i = 0; i < 6; i++) {
        const int x  = x0 + i;
        const int xx = x + 2;
        #pragma unroll
        for (int dy = 0; dy < 5; dy++) {
            const int yy = y + dy - 2;
            win[dy][4] = (xx < WW && yy >= 0 && yy < HH)
                       ? vb[(size_t)(yy * WW + xx) * EMBED + c] : 0.f;
        }
        float sum = bv;
        #pragma unroll
        for (int dy = 0; dy < 5; dy++)
            #pragma unroll
            for (int j = 0; j < 5; j++)
                sum = fmaf(win[dy][j], wr[dy * 5 + j], sum);
        ob[(size_t)x * EMBED + c] = sum;
        #pragma unroll
        for (int dy = 0; dy < 5; dy++)
            #pragma unroll
            for (int j = 0; j < 4; j++)
                win[dy][j] = win[dy][j + 1];
    }
}

// ---------------------------------------------------------------------------
// Attention v11: mask staged via cp.async into smem (2-deep ring, coalesced
// fill, conflict-free LDS.64 fragment reads at stride 72). K/V 3-deep ring,
// fp16 QK+PV, base-2 fp16x2 softmax, l via ones-mma. Dynamic smem 104.4 KB.
// Group discipline: per tile issue [M(t+1)] then [KV(t+2)]; wait_group 1 at
// tile top leaves only the newest group pending => M(t) and KV(t) resident.
// ---------------------------------------------------------------------------
__global__ void __launch_bounds__(256, 2)
attn_kernel(const float* __restrict__ mask)
{
    extern __shared__ __align__(16) uint32_t dsm[];

    const int tid  = threadIdx.x;
    const int warp = tid >> 5;
    const int lane = tid & 31;
    const int g    = lane >> 2;
    const int t4   = lane & 3;
    const int li   = lane & 7;
    const int sub  = lane >> 3;

    const int b  = blockIdx.x;
    const int q0 = blockIdx.y * TQ;
    const int h  = blockIdx.z;
    const int qw = q0 + warp * 16;

    const __half* Qg = g_qh + (size_t)(b * NTOK + qw) * EMBED + h * HD;
    const __half* Kg = g_kh + (size_t)b * NTOK * EMBED + h * HD;
    const __half* Vg = g_vh + (size_t)b * NTOK * EMBED + h * HD;
    const float*  Mb = mask + (size_t)h * NTOK * NTOK + (size_t)q0 * NTOK;

    const int lr  = tid >> 2;            // KV tile row 0..63
    const int lc8 = (tid & 3) * 8;       // half chunk

    const uint32_t smem0 = (uint32_t)__cvta_generic_to_shared(dsm);
    const uint32_t ksm = smem0 + KOFF * 4;
    const uint32_t vsm = smem0 + VOFF * 4;
    const uint32_t msm = smem0 + MOFF * 4;
    const uint32_t TB = TK * KVH * 4;    // 5120 per KV buffer
    const uint32_t MB = TQ * MSTR * 4;   // 36864 per mask buffer
    const float* m_f = (const float*)(dsm + MOFF);

    const uint32_t aK0 = ksm + ((sub >> 1) * 8 + li) * (KVH * 4) + (sub & 1) * 16;
    const uint32_t aV0 = vsm + ((sub & 1) * 8 + li) * (KVH * 4) + (sub >> 1) * 16;

    #define ISSUE_KV(t)                                                       \
    {                                                                         \
        const int _buf = (t) % 3;                                             \
        const size_t ro = (size_t)((t) * TK + lr) * EMBED + lc8;              \
        cp16(ksm + _buf * TB + lr * (KVH * 4) + lc8 * 2, &Kg[ro]);            \
        cp16(vsm + _buf * TB + lr * (KVH * 4) + lc8 * 2, &Vg[ro]);            \
        asm volatile("cp.async.commit_group;");                               \
    }

    #define ISSUE_M(t)                                                        \
    {                                                                         \
        const uint32_t _mb = msm + ((t) & 1) * MB;                            \
        _Pragma("unroll")                                                     \
        for (int j = 0; j < 8; j++) {                                         \
            const int idx = j * 256 + tid;                                    \
            const int q = idx >> 4, c4 = (idx & 15) << 2;                     \
            cp16(_mb + ((q * MSTR + c4) << 2),                                \
                 &Mb[(size_t)q * NTOK + (t) * TK + c4]);                      \
        }                                                                     \
        asm volatile("cp.async.commit_group;");                               \
    }

    // prologue: groups [M0][KV0][KV1]
    ISSUE_M(0)
    ISSUE_KV(0)
    ISSUE_KV(1)

    // Q fragments (fp16, pre-scaled by log2e)
    uint32_t qa[2][4];
    #pragma unroll
    for (int kc = 0; kc < 2; kc++) {
        qa[kc][0] = *(const uint32_t*)&Qg[(size_t)g * EMBED + kc * 16 + 2 * t4];
        qa[kc][1] = *(const uint32_t*)&Qg[(size_t)(g + 8) * EMBED + kc * 16 + 2 * t4];
        qa[kc][2] = *(const uint32_t*)&Qg[(size_t)g * EMBED + kc * 16 + 2 * t4 + 8];
        qa[kc][3] = *(const uint32_t*)&Qg[(size_t)(g + 8) * EMBED + kc * 16 + 2 * t4 + 8];
    }

    float acc[4][4] = {};
    float lacc[4] = {};

    #pragma unroll 1
    for (int it = 0; it < NKT; it++) {
        const int buf = it % 3;
        asm volatile("cp.async.wait_group 1;");   // M(it), KV(it) resident
        __syncthreads();                          // + ring slots free

        if (it + 1 < NKT) ISSUE_M(it + 1)
        else asm volatile("cp.async.commit_group;");
        if (it + 2 < NKT) ISSUE_KV(it + 2)
        else asm volatile("cp.async.commit_group;");

        // ---- QK^T fp16 (base-2 exponents) ----
        float c[8][4] = {};
        const uint32_t aK = aK0 + buf * TB;
        #pragma unroll
        for (int kc = 0; kc < 2; kc++) {
            #pragma unroll
            for (int p = 0; p < 4; p++) {
                uint32_t r0, r1, r2, r3;
                ldsm4(r0, r1, r2, r3, aK + p * (16 * KVH * 4) + kc * 32);
                mma_f16(c[2 * p][0], c[2 * p][1], c[2 * p][2], c[2 * p][3],
                        qa[kc][0], qa[kc][1], qa[kc][2], qa[kc][3], r0, r1);
                mma_f16(c[2 * p + 1][0], c[2 * p + 1][1],
                        c[2 * p + 1][2], c[2 * p + 1][3],
                        qa[kc][0], qa[kc][1], qa[kc][2], qa[kc][3], r2, r3);
            }
        }

        // ---- P = 2^(c + mask*log2e); mask fragments from smem (LDS.64) ----
        const float* mt = m_f + ((it & 1) * TQ + warp * 16 + g) * MSTR + 2 * t4;
        uint32_t ph[8][2];
        #pragma unroll
        for (int n0 = 0; n0 < 8; n0++) {
            float2 mA = *(const float2*)(mt + n0 * 8);
            float2 mB = *(const float2*)(mt + n0 * 8 + 8 * MSTR);
            float t0 = fmaf(mA.x, LOG2E, c[n0][0]);
            float t1 = fmaf(mA.y, LOG2E, c[n0][1]);
            float t2 = fmaf(mB.x, LOG2E, c[n0][2]);
            float t3 = fmaf(mB.y, LOG2E, c[n0][3]);
            ph[n0][0] = ex2_h2(pack_h2(t0, t1));
            ph[n0][1] = ex2_h2(pack_h2(t2, t3));
        }

        // ---- PV fp16 + ones-column l mma ----
        const uint32_t aV = aV0 + buf * TB;
        #pragma unroll
        for (int kc = 0; kc < 4; kc++) {
            const uint32_t pa0 = ph[2 * kc][0];
            const uint32_t pa1 = ph[2 * kc][1];
            const uint32_t pa2 = ph[2 * kc + 1][0];
            const uint32_t pa3 = ph[2 * kc + 1][1];
            #pragma unroll
            for (int ha = 0; ha < 2; ha++) {
                uint32_t r0, r1, r2, r3;
                ldsm4t(r0, r1, r2, r3,
                       aV + kc * (16 * KVH * 4) + ha * 32);
                mma_f16(acc[2 * ha][0], acc[2 * ha][1],
                        acc[2 * ha][2], acc[2 * ha][3],
                        pa0, pa1, pa2, pa3, r0, r1);
                mma_f16(acc[2 * ha + 1][0], acc[2 * ha + 1][1],
                        acc[2 * ha + 1][2], acc[2 * ha + 1][3],
                        pa0, pa1, pa2, pa3, r2, r3);
            }
            mma_f16(lacc[0], lacc[1], lacc[2], lacc[3],
                    pa0, pa1, pa2, pa3, H2_ONES, H2_ONES);
        }
    }
    #undef ISSUE_KV
    #undef ISSUE_M

    const float inv0 = 1.0f / lacc[0];
    const float inv1 = 1.0f / lacc[2];
    const float* Lg = g_lepe + (size_t)(b * NTOK + qw) * EMBED + h * HD;
    float* Og = g_ao + (size_t)(b * NTOK + qw) * EMBED + h * HD;
    #pragma unroll
    for (int n = 0; n < 4; n++) {
        const int off = n * 8 + 2 * t4;
        float2 lp0 = *(const float2*)&Lg[(size_t)g * EMBED + off];
        float2 lp1 = *(const float2*)&Lg[(size_t)(g + 8) * EMBED + off];
        float2 o0, o1;
        o0.x = __uint_as_float(f2tf32(acc[n][0] * inv0 + lp0.x));
        o0.y = __uint_as_float(f2tf32(acc[n][1] * inv0 + lp0.y));
        o1.x = __uint_as_float(f2tf32(acc[n][2] * inv1 + lp1.x));
        o1.y = __uint_as_float(f2tf32(acc[n][3] * inv1 + lp1.y));
        *(float2*)&Og[(size_t)g * EMBED + off] = o0;
        *(float2*)&Og[(size_t)(g + 8) * EMBED + off] = o1;
    }
}

// ---------------------------------------------------------------------------
extern "C" void kernel_launch(void* const* d_in, const int* in_sizes, int n_in,
                              void* d_out, int out_size)
{
    const float* x      = (const float*)d_in[0];
    const float* sin_t  = (const float*)d_in[1];
    const float* cos_t  = (const float*)d_in[2];
    const float* mask   = (const float*)d_in[3];
    const float* bq     = (const float*)d_in[5];
    const float* bk     = (const float*)d_in[7];
    const float* bv     = (const float*)d_in[9];
    const float* lepe_w = (const float*)d_in[10];
    const float* lepe_b = (const float*)d_in[11];
    const float* bout   = (const float*)d_in[13];
    float* out = (float*)d_out;

    const int M = BATCH * NTOK;   // 9216

    static int smem_set = 0;
    if (!smem_set) {
        cudaFuncSetAttribute(qkv_gemm_t,
            cudaFuncAttributeMaxDynamicSharedMemorySize, GEMM_SMEM);
        cudaFuncSetAttribute(out_gemm_t,
            cudaFuncAttributeMaxDynamicSharedMemorySize, GEMM_SMEM);
        cudaFuncSetAttribute(attn_kernel,
            cudaFuncAttributeMaxDynamicSharedMemorySize, ATTN_SMEM);
        smem_set = 1;
    }

    round_all<<<NXB + NWB, 256>>>(x, (const float*)d_in[4],
        (const float*)d_in[6], (const float*)d_in[8], (const float*)d_in[12]);
    qkv_gemm_t<<<dim3(12, M / GBM), 256, GEMM_SMEM>>>(bq, bk, bv, sin_t, cos_t);
    lepe_kernel<<<dim3(HH, BATCH, 8), 256>>>(lepe_w, lepe_b);
    attn_kernel<<<dim3(BATCH, NTOK / TQ, HEADS), 256, ATTN_SMEM>>>(mask);
    out_gemm_t<<<dim3(4, M / GBM), 256, GEMM_SMEM>>>(bout, out);
}